// round 9
// baseline (speedup 1.0000x reference)
#include <cuda_runtime.h>
#include <cstdint>
#include <cstddef>

#define Nn 50000
#define Ee 1600000
#define Gg 128
#define Hh 64

// ---- scratch (device globals) ----
__device__ float g_z[(size_t)5 * Nn * Hh];     // 64 MB: z_k = segment_sum(ea_k * act(h[src]))
__device__ float g_h0[(size_t)Nn * Hh];        // ping
__device__ float g_h1[(size_t)Nn * Hh];        // pong
__device__ float g_pool[Gg * 2 * Hh];

// dst-CSR sort scratch (24 B/edge, split)
__device__ int    g_cnt[Nn];
__device__ int    g_cursor[Nn];
__device__ int    g_rowptr[Nn + 1];
__device__ float4 g_er0[Ee];                   // {src, w0, w1, w2}
__device__ float2 g_er1[Ee];                   // {w3, w4}

// ============================================================
// counting sort by dst: hist -> scan -> permute
// ============================================================
__global__ void zero_cnt_kernel(int* __restrict__ cnt)
{
    unsigned i = blockIdx.x * 256u + threadIdx.x;
    if (i < (unsigned)Nn) cnt[i] = 0;
}

__global__ void hist_kernel(const int* __restrict__ ei, int* __restrict__ cnt)
{
    unsigned e = blockIdx.x * 256u + threadIdx.x;
    if (e < (unsigned)Ee) atomicAdd(&cnt[__ldg(ei + Ee + e)], 1);  // dst
}

__global__ void scan_kernel(const int* __restrict__ cnt,
                            int* __restrict__ cursor,
                            int* __restrict__ rowptr)
{
    __shared__ int tsum[1024];
    const int t  = threadIdx.x;
    const int CH = (Nn + 1023) / 1024;  // 49
    const int base = t * CH;

    int s = 0;
#pragma unroll 1
    for (int i = 0; i < CH; ++i) {
        int idx = base + i;
        if (idx < Nn) s += cnt[idx];
    }
    tsum[t] = s;
    __syncthreads();
    for (int o = 1; o < 1024; o <<= 1) {
        int u = (t >= o) ? tsum[t - o] : 0;
        __syncthreads();
        tsum[t] += u;
        __syncthreads();
    }
    int run = tsum[t] - s;  // exclusive
#pragma unroll 1
    for (int i = 0; i < CH; ++i) {
        int idx = base + i;
        if (idx < Nn) {
            cursor[idx] = run;
            rowptr[idx] = run;
            run += cnt[idx];
        }
    }
    if (t == 0) rowptr[Nn] = Ee;
}

__global__ void permute_kernel(const int* __restrict__ ei,
                               const float* __restrict__ ea,
                               int* __restrict__ cursor,
                               float4* __restrict__ er0,
                               float2* __restrict__ er1)
{
    unsigned e = blockIdx.x * 256u + threadIdx.x;
    if (e >= (unsigned)Ee) return;
    int src = __ldg(ei + e);
    int dst = __ldg(ei + Ee + e);
    const float* p = ea + (size_t)e * 5;
    float w0 = __ldg(p), w1 = __ldg(p + 1), w2 = __ldg(p + 2),
          w3 = __ldg(p + 3), w4 = __ldg(p + 4);
    int pos = atomicAdd(&cursor[dst], 1);
    er0[pos] = make_float4(__int_as_float(src), w0, w1, w2);
    er1[pos] = make_float2(w3, w4);
}

// ============================================================
// Aggregate (H=64): one warp per dst node; 4 edges in flight.
// par = lane>>3 selects edge stream; hg = lane&7 covers feats 8hg..8hg+7
// (two float4 gathers). Streams combined via shfl_xor(8,16).
// ============================================================
__global__ void aggregate64_kernel(const int* __restrict__ rowptr,
                                   const float4* __restrict__ er0,
                                   const float2* __restrict__ er1,
                                   const float* __restrict__ x,
                                   float* __restrict__ z)
{
    int dst = blockIdx.x * 8 + (threadIdx.x >> 5);
    if (dst >= Nn) return;
    const int lane = threadIdx.x & 31;
    const int hg   = lane & 7;    // feat group: feats 8*hg..8*hg+7
    const int par  = lane >> 3;   // edge stream 0..3
    const int beg = __ldg(rowptr + dst);
    const int end = __ldg(rowptr + dst + 1);

    float4 aA[5], aB[5];
#pragma unroll
    for (int k = 0; k < 5; ++k) {
        aA[k] = make_float4(0.f,0.f,0.f,0.f);
        aB[k] = make_float4(0.f,0.f,0.f,0.f);
    }

    for (int e = beg + par; e < end; e += 4) {
        float4 r0 = __ldg(er0 + e);
        float2 r1 = __ldg(er1 + e);
        int src = __float_as_int(r0.x);
        const float* xp = x + (size_t)src * 64 + hg * 8;
        float4 vA = __ldg((const float4*)xp);
        float4 vB = __ldg((const float4*)(xp + 4));
        float w;
        w = r0.y;
        aA[0].x += w*vA.x; aA[0].y += w*vA.y; aA[0].z += w*vA.z; aA[0].w += w*vA.w;
        aB[0].x += w*vB.x; aB[0].y += w*vB.y; aB[0].z += w*vB.z; aB[0].w += w*vB.w;
        w = r0.z;
        aA[1].x += w*vA.x; aA[1].y += w*vA.y; aA[1].z += w*vA.z; aA[1].w += w*vA.w;
        aB[1].x += w*vB.x; aB[1].y += w*vB.y; aB[1].z += w*vB.z; aB[1].w += w*vB.w;
        w = r0.w;
        aA[2].x += w*vA.x; aA[2].y += w*vA.y; aA[2].z += w*vA.z; aA[2].w += w*vA.w;
        aB[2].x += w*vB.x; aB[2].y += w*vB.y; aB[2].z += w*vB.z; aB[2].w += w*vB.w;
        w = r1.x;
        aA[3].x += w*vA.x; aA[3].y += w*vA.y; aA[3].z += w*vA.z; aA[3].w += w*vA.w;
        aB[3].x += w*vB.x; aB[3].y += w*vB.y; aB[3].z += w*vB.z; aB[3].w += w*vB.w;
        w = r1.y;
        aA[4].x += w*vA.x; aA[4].y += w*vA.y; aA[4].z += w*vA.z; aA[4].w += w*vA.w;
        aB[4].x += w*vB.x; aB[4].y += w*vB.y; aB[4].z += w*vB.z; aB[4].w += w*vB.w;
    }

    // combine 4 edge streams: lanes with same hg differ in bits 3,4
#define CMB(f) f += __shfl_xor_sync(0xffffffffu, f, 8); f += __shfl_xor_sync(0xffffffffu, f, 16)
#pragma unroll
    for (int k = 0; k < 5; ++k) {
        CMB(aA[k].x); CMB(aA[k].y); CMB(aA[k].z); CMB(aA[k].w);
        CMB(aB[k].x); CMB(aB[k].y); CMB(aB[k].z); CMB(aB[k].w);
    }
#undef CMB

    if (par == 0) {
        const size_t KS = (size_t)Nn * 64;
        float* zp = z + (size_t)dst * 64 + hg * 8;
#pragma unroll
        for (int k = 0; k < 5; ++k) {
            *(float4*)(zp + k * KS)     = aA[k];
            *(float4*)(zp + k * KS + 4) = aB[k];
        }
    }
}

// ============================================================
// Aggregate (F=16, layer 1, raw x): 8 edges in flight.
// par = lane>>2 (stream 0..7); fg = lane&3 covers feats 4fg..4fg+3.
// ============================================================
__global__ void aggregate16_kernel(const int* __restrict__ rowptr,
                                   const float4* __restrict__ er0,
                                   const float2* __restrict__ er1,
                                   const float* __restrict__ x,
                                   float* __restrict__ z)
{
    int dst = blockIdx.x * 8 + (threadIdx.x >> 5);
    if (dst >= Nn) return;
    const int lane = threadIdx.x & 31;
    const int fg   = lane & 3;    // feats 4fg..4fg+3
    const int par  = lane >> 2;   // edge stream 0..7
    const int beg = __ldg(rowptr + dst);
    const int end = __ldg(rowptr + dst + 1);

    float4 a[5];
#pragma unroll
    for (int k = 0; k < 5; ++k) a[k] = make_float4(0.f,0.f,0.f,0.f);

    for (int e = beg + par; e < end; e += 8) {
        float4 r0 = __ldg(er0 + e);
        float2 r1 = __ldg(er1 + e);
        int src = __float_as_int(r0.x);
        float4 v = __ldg((const float4*)(x + (size_t)src * 16 + fg * 4));
        float w;
        w = r0.y; a[0].x += w*v.x; a[0].y += w*v.y; a[0].z += w*v.z; a[0].w += w*v.w;
        w = r0.z; a[1].x += w*v.x; a[1].y += w*v.y; a[1].z += w*v.z; a[1].w += w*v.w;
        w = r0.w; a[2].x += w*v.x; a[2].y += w*v.y; a[2].z += w*v.z; a[2].w += w*v.w;
        w = r1.x; a[3].x += w*v.x; a[3].y += w*v.y; a[3].z += w*v.z; a[3].w += w*v.w;
        w = r1.y; a[4].x += w*v.x; a[4].y += w*v.y; a[4].z += w*v.z; a[4].w += w*v.w;
    }

#define CMB(f) f += __shfl_xor_sync(0xffffffffu, f, 4); \
               f += __shfl_xor_sync(0xffffffffu, f, 8); \
               f += __shfl_xor_sync(0xffffffffu, f, 16)
#pragma unroll
    for (int k = 0; k < 5; ++k) {
        CMB(a[k].x); CMB(a[k].y); CMB(a[k].z); CMB(a[k].w);
    }
#undef CMB

    if (par == 0) {
        const size_t KS = (size_t)Nn * 16;
        float* zp = z + (size_t)dst * 16 + fg * 4;
#pragma unroll
        for (int k = 0; k < 5; ++k)
            *(float4*)(zp + k * KS) = a[k];
    }
}

// ============================================================
// GEMM-sum: h[n] = relu( sum_k z_k[n] @ W[k] + b )
// 128 nodes x 64 outs / CTA, 256 threads, 8x4 register tile.
// Dynamic smem: zsT[KD][132] + ws[KD*64]. 4 CTAs/SM.
// ============================================================
template<int KD>
__global__ void __launch_bounds__(256, 4)
gemmsum_kernel(const float* __restrict__ z,
               const float* __restrict__ W,
               const float* __restrict__ b,
               float* __restrict__ h)
{
    extern __shared__ float smem[];
    float* zsT = smem;               // [KD][132], node-major rows
    float* ws  = smem + KD * 132;    // [KD*64]

    const int t  = threadIdx.x;
    const int n0 = blockIdx.x * 128;
    const int tx = t & 15;           // cols 4tx..4tx+3
    const int ty = t >> 4;           // nodes ty*8..ty*8+7

    float4 acc[8];
#pragma unroll
    for (int r = 0; r < 8; ++r) acc[r] = make_float4(0.f, 0.f, 0.f, 0.f);

#pragma unroll 1
    for (int k = 0; k < 5; ++k) {
        __syncthreads();
        const float* zk = z + (size_t)k * Nn * KD;
        for (int idx = t; idx < 128 * KD; idx += 256) {
            int node = idx / KD;
            int c    = idx - node * KD;
            int n    = n0 + node;
            zsT[c * 132 + node] = (n < Nn) ? zk[(size_t)n * KD + c] : 0.f;
        }
        for (int idx = t; idx < KD * 64; idx += 256)
            ws[idx] = __ldg(W + k * KD * 64 + idx);
        __syncthreads();

#pragma unroll 8
        for (int kk = 0; kk < KD; ++kk) {
            float4 xa = *(const float4*)&zsT[kk * 132 + ty * 8];
            float4 xb = *(const float4*)&zsT[kk * 132 + ty * 8 + 4];
            float4 wv = *(const float4*)&ws[kk * 64 + tx * 4];
            acc[0].x += xa.x * wv.x; acc[0].y += xa.x * wv.y; acc[0].z += xa.x * wv.z; acc[0].w += xa.x * wv.w;
            acc[1].x += xa.y * wv.x; acc[1].y += xa.y * wv.y; acc[1].z += xa.y * wv.z; acc[1].w += xa.y * wv.w;
            acc[2].x += xa.z * wv.x; acc[2].y += xa.z * wv.y; acc[2].z += xa.z * wv.z; acc[2].w += xa.z * wv.w;
            acc[3].x += xa.w * wv.x; acc[3].y += xa.w * wv.y; acc[3].z += xa.w * wv.z; acc[3].w += xa.w * wv.w;
            acc[4].x += xb.x * wv.x; acc[4].y += xb.x * wv.y; acc[4].z += xb.x * wv.z; acc[4].w += xb.x * wv.w;
            acc[5].x += xb.y * wv.x; acc[5].y += xb.y * wv.y; acc[5].z += xb.y * wv.z; acc[5].w += xb.y * wv.w;
            acc[6].x += xb.z * wv.x; acc[6].y += xb.z * wv.y; acc[6].z += xb.z * wv.z; acc[6].w += xb.z * wv.w;
            acc[7].x += xb.w * wv.x; acc[7].y += xb.w * wv.y; acc[7].z += xb.w * wv.z; acc[7].w += xb.w * wv.w;
        }
    }

    float4 bb = *(const float4*)&b[tx * 4];
#pragma unroll
    for (int r = 0; r < 8; ++r) {
        int nl = n0 + ty * 8 + r;
        if (nl >= Nn) break;
        float4 o;
        o.x = fmaxf(acc[r].x + bb.x, 0.f);
        o.y = fmaxf(acc[r].y + bb.y, 0.f);
        o.z = fmaxf(acc[r].z + bb.z, 0.f);
        o.w = fmaxf(acc[r].w + bb.w, 0.f);
        *(float4*)&h[(size_t)nl * 64 + tx * 4] = o;
    }
}

// ============================================================
// Pooling: h already relu'd; sum & max per analytic graph ranges.
// ============================================================
__global__ void pool_kernel(const float* __restrict__ h, float* __restrict__ pooled)
{
    __shared__ float ss[4][64];
    __shared__ float sm[4][64];
    int g     = blockIdx.x;
    int f     = threadIdx.x & 63;
    int strip = threadIdx.x >> 6;
    int start = (g * Nn + Gg - 1) / Gg;
    int end   = ((g + 1) * Nn + Gg - 1) / Gg;

    float s = 0.f, m = 0.f;  // h >= 0
    for (int n = start + strip; n < end; n += 4) {
        float v = __ldg(h + (size_t)n * 64 + f);
        s += v;
        m = fmaxf(m, v);
    }
    ss[strip][f] = s;
    sm[strip][f] = m;
    __syncthreads();
    if (strip == 0) {
        s = ss[0][f] + ss[1][f] + ss[2][f] + ss[3][f];
        m = fmaxf(fmaxf(sm[0][f], sm[1][f]), fmaxf(sm[2][f], sm[3][f]));
        pooled[g * 128 + f]      = s;
        pooled[g * 128 + 64 + f] = m;
    }
}

// ============================================================
// Head: BN -> FC -> log_softmax
// ============================================================
__global__ void head_kernel(const float* __restrict__ pooled,
                            const float* __restrict__ gam,
                            const float* __restrict__ bet,
                            const float* __restrict__ mean,
                            const float* __restrict__ var,
                            const float* __restrict__ fw,
                            const float* __restrict__ fb,
                            float* __restrict__ out)
{
    int g    = blockIdx.x;
    int lane = threadIdx.x;

    float pn[4];
#pragma unroll
    for (int i = 0; i < 4; ++i) {
        int c = lane + 32 * i;
        float p = __ldg(pooled + g * 128 + c);
        float inv = 1.f / sqrtf(__ldg(var + c) + 1e-5f);
        pn[i] = (p - __ldg(mean + c)) * inv * __ldg(gam + c) + __ldg(bet + c);
    }

    float logits[6];
#pragma unroll
    for (int j = 0; j < 6; ++j) {
        float s = 0.f;
#pragma unroll
        for (int i = 0; i < 4; ++i)
            s += pn[i] * __ldg(fw + (lane + 32 * i) * 6 + j);
#pragma unroll
        for (int o = 16; o; o >>= 1)
            s += __shfl_xor_sync(0xffffffffu, s, o);
        logits[j] = s + __ldg(fb + j);
    }

    if (lane == 0) {
        float m = logits[0];
#pragma unroll
        for (int j = 1; j < 6; ++j) m = fmaxf(m, logits[j]);
        float se = 0.f;
#pragma unroll
        for (int j = 0; j < 6; ++j) se += expf(logits[j] - m);
        float lse = m + logf(se);
#pragma unroll
        for (int j = 0; j < 6; ++j) out[g * 6 + j] = logits[j] - lse;
    }
}

// ============================================================
extern "C" void kernel_launch(void* const* d_in, const int* in_sizes, int n_in,
                              void* d_out, int out_size)
{
    const float* x   = (const float*)d_in[0];
    const int*   ei  = (const int*)  d_in[1];
    const float* ea  = (const float*)d_in[2];
    const float* W1  = (const float*)d_in[4];
    const float* b1  = (const float*)d_in[5];
    const float* W2  = (const float*)d_in[6];
    const float* b2  = (const float*)d_in[7];
    const float* W3  = (const float*)d_in[8];
    const float* b3  = (const float*)d_in[9];
    const float* W4  = (const float*)d_in[10];
    const float* b4  = (const float*)d_in[11];
    const float* bng = (const float*)d_in[12];
    const float* bnb = (const float*)d_in[13];
    const float* bnm = (const float*)d_in[14];
    const float* bnv = (const float*)d_in[15];
    const float* fw  = (const float*)d_in[16];
    const float* fb  = (const float*)d_in[17];
    float* out = (float*)d_out;

    float *zb, *h0, *h1, *pl;
    int *cnt, *cur, *rp;
    float4* er0;
    float2* er1;
    cudaGetSymbolAddress((void**)&zb, g_z);
    cudaGetSymbolAddress((void**)&h0, g_h0);
    cudaGetSymbolAddress((void**)&h1, g_h1);
    cudaGetSymbolAddress((void**)&pl, g_pool);
    cudaGetSymbolAddress((void**)&cnt, g_cnt);
    cudaGetSymbolAddress((void**)&cur, g_cursor);
    cudaGetSymbolAddress((void**)&rp, g_rowptr);
    cudaGetSymbolAddress((void**)&er0, g_er0);
    cudaGetSymbolAddress((void**)&er1, g_er1);

    const int EB = (Ee + 255) / 256;        // 6250
    const int GB = (Nn + 127) / 128;        // 391
    const int AB = (Nn + 7) / 8;            // 6250 (one warp per dst)

    const int SM16 = (16 * 132 + 16 * 64) * 4;   // 12544 B
    const int SM64 = (64 * 132 + 64 * 64) * 4;   // 50176 B
    static int smem_set = 0;
    if (!smem_set) {
        cudaFuncSetAttribute(gemmsum_kernel<16>, cudaFuncAttributeMaxDynamicSharedMemorySize, SM16);
        cudaFuncSetAttribute(gemmsum_kernel<64>, cudaFuncAttributeMaxDynamicSharedMemorySize, SM64);
        smem_set = 1;
    }

    // ---- counting sort of edges by dst -> CSR ----
    zero_cnt_kernel<<<(Nn + 255) / 256, 256>>>(cnt);
    hist_kernel<<<EB, 256>>>(ei, cnt);
    scan_kernel<<<1, 1024>>>(cnt, cur, rp);
    permute_kernel<<<EB, 256>>>(ei, ea, cur, er0, er1);

    // ---- layer 1 (in: x [N,16], raw) ----
    aggregate16_kernel<<<AB, 256>>>(rp, er0, er1, x, zb);
    gemmsum_kernel<16><<<GB, 256, SM16>>>(zb, W1, b1, h0);
    // ---- layer 2 ----
    aggregate64_kernel<<<AB, 256>>>(rp, er0, er1, h0, zb);
    gemmsum_kernel<64><<<GB, 256, SM64>>>(zb, W2, b2, h1);
    // ---- layer 3 ----
    aggregate64_kernel<<<AB, 256>>>(rp, er0, er1, h1, zb);
    gemmsum_kernel<64><<<GB, 256, SM64>>>(zb, W3, b3, h0);
    // ---- layer 4 ----
    aggregate64_kernel<<<AB, 256>>>(rp, er0, er1, h0, zb);
    gemmsum_kernel<64><<<GB, 256, SM64>>>(zb, W4, b4, h1);

    pool_kernel<<<Gg, 256>>>(h1, pl);
    head_kernel<<<Gg, 32>>>(pl, bng, bnb, bnm, bnv, fw, fb, out);
}

// round 10
// speedup vs baseline: 1.1093x; 1.1093x over previous
#include <cuda_runtime.h>
#include <cstdint>
#include <cstddef>

#define Nn 50000
#define Ee 1600000
#define Gg 128
#define Hh 64

// ---- scratch (device globals) ----
__device__ float g_z[(size_t)5 * Nn * Hh];     // 64 MB: z_k = segment_sum(ea_k * act(h[src]))
__device__ float g_h0[(size_t)Nn * Hh];        // ping
__device__ float g_h1[(size_t)Nn * Hh];        // pong
__device__ float g_pool[Gg * 2 * Hh];

// dst-CSR sort scratch (24 B/edge, split)
__device__ int    g_cnt[Nn];
__device__ int    g_cursor[Nn];
__device__ int    g_rowptr[Nn + 1];
__device__ float4 g_er0[Ee];                   // {src, w0, w1, w2}
__device__ float2 g_er1[Ee];                   // {w3, w4}

// ============================================================
// counting sort by dst: hist -> scan -> permute
// ============================================================
__global__ void zero_cnt_kernel(int* __restrict__ cnt)
{
    unsigned i = blockIdx.x * 256u + threadIdx.x;
    if (i < (unsigned)Nn) cnt[i] = 0;
}

__global__ void hist_kernel(const int* __restrict__ ei, int* __restrict__ cnt)
{
    unsigned e = blockIdx.x * 256u + threadIdx.x;
    if (e < (unsigned)Ee) atomicAdd(&cnt[__ldg(ei + Ee + e)], 1);  // dst
}

__global__ void scan_kernel(const int* __restrict__ cnt,
                            int* __restrict__ cursor,
                            int* __restrict__ rowptr)
{
    __shared__ int tsum[1024];
    const int t  = threadIdx.x;
    const int CH = (Nn + 1023) / 1024;  // 49
    const int base = t * CH;

    int s = 0;
#pragma unroll 1
    for (int i = 0; i < CH; ++i) {
        int idx = base + i;
        if (idx < Nn) s += cnt[idx];
    }
    tsum[t] = s;
    __syncthreads();
    for (int o = 1; o < 1024; o <<= 1) {
        int u = (t >= o) ? tsum[t - o] : 0;
        __syncthreads();
        tsum[t] += u;
        __syncthreads();
    }
    int run = tsum[t] - s;  // exclusive
#pragma unroll 1
    for (int i = 0; i < CH; ++i) {
        int idx = base + i;
        if (idx < Nn) {
            cursor[idx] = run;
            rowptr[idx] = run;
            run += cnt[idx];
        }
    }
    if (t == 0) rowptr[Nn] = Ee;
}

// 2 independent edges per thread: doubles the number of
// atomic->scattered-store chains in flight per thread.
__global__ void permute_kernel(const int* __restrict__ ei,
                               const float* __restrict__ ea,
                               int* __restrict__ cursor,
                               float4* __restrict__ er0,
                               float2* __restrict__ er1)
{
    unsigned base = blockIdx.x * 512u + threadIdx.x;
#pragma unroll
    for (int j = 0; j < 2; ++j) {
        unsigned e = base + (unsigned)j * 256u;
        if (e >= (unsigned)Ee) continue;
        int src = __ldg(ei + e);
        int dst = __ldg(ei + Ee + e);
        const float* p = ea + (size_t)e * 5;
        float w0 = __ldg(p), w1 = __ldg(p + 1), w2 = __ldg(p + 2),
              w3 = __ldg(p + 3), w4 = __ldg(p + 4);
        int pos = atomicAdd(&cursor[dst], 1);
        er0[pos] = make_float4(__int_as_float(src), w0, w1, w2);
        er1[pos] = make_float2(w3, w4);
    }
}

// ============================================================
// Aggregate (H=64): one warp per dst node; 2 edges in flight.
// Lanes 0-15 process even edges, 16-31 odd edges; each lane = 4 feats
// (float4 gather). Halves combined via shfl_xor(16) at the end.
// ============================================================
__global__ void aggregate64_kernel(const int* __restrict__ rowptr,
                                   const float4* __restrict__ er0,
                                   const float2* __restrict__ er1,
                                   const float* __restrict__ x,
                                   float* __restrict__ z)
{
    int dst = blockIdx.x * 8 + (threadIdx.x >> 5);
    if (dst >= Nn) return;
    const int lane = threadIdx.x & 31;
    const int hl   = lane & 15;   // feat group: feats 4*hl..4*hl+3
    const int par  = lane >> 4;   // edge parity
    const int beg = __ldg(rowptr + dst);
    const int end = __ldg(rowptr + dst + 1);

    float4 a0 = {0.f,0.f,0.f,0.f}, a1 = a0, a2 = a0, a3 = a0, a4 = a0;

#pragma unroll 2
    for (int e = beg + par; e < end; e += 2) {
        float4 r0 = __ldg(er0 + e);
        float2 r1 = __ldg(er1 + e);
        int src = __float_as_int(r0.x);
        float4 v = __ldg((const float4*)(x + (size_t)src * 64 + hl * 4));
        a0.x += r0.y*v.x; a0.y += r0.y*v.y; a0.z += r0.y*v.z; a0.w += r0.y*v.w;
        a1.x += r0.z*v.x; a1.y += r0.z*v.y; a1.z += r0.z*v.z; a1.w += r0.z*v.w;
        a2.x += r0.w*v.x; a2.y += r0.w*v.y; a2.z += r0.w*v.z; a2.w += r0.w*v.w;
        a3.x += r1.x*v.x; a3.y += r1.x*v.y; a3.z += r1.x*v.z; a3.w += r1.x*v.w;
        a4.x += r1.y*v.x; a4.y += r1.y*v.y; a4.z += r1.y*v.z; a4.w += r1.y*v.w;
    }

    // combine parity halves (same feats live at lane and lane^16)
#define CMB(f) f += __shfl_xor_sync(0xffffffffu, f, 16)
    CMB(a0.x); CMB(a0.y); CMB(a0.z); CMB(a0.w);
    CMB(a1.x); CMB(a1.y); CMB(a1.z); CMB(a1.w);
    CMB(a2.x); CMB(a2.y); CMB(a2.z); CMB(a2.w);
    CMB(a3.x); CMB(a3.y); CMB(a3.z); CMB(a3.w);
    CMB(a4.x); CMB(a4.y); CMB(a4.z); CMB(a4.w);
#undef CMB

    if (par == 0) {
        const size_t KS = (size_t)Nn * 64;
        float* zp = z + (size_t)dst * 64 + hl * 4;
        *(float4*)(zp)        = a0;
        *(float4*)(zp + KS)   = a1;
        *(float4*)(zp + 2*KS) = a2;
        *(float4*)(zp + 3*KS) = a3;
        *(float4*)(zp + 4*KS) = a4;
    }
}

// ============================================================
// Aggregate (F=16, layer 1, raw x): warp splits in 2 halves over edges.
// ============================================================
__global__ void aggregate16_kernel(const int* __restrict__ rowptr,
                                   const float4* __restrict__ er0,
                                   const float2* __restrict__ er1,
                                   const float* __restrict__ x,
                                   float* __restrict__ z)
{
    int dst = blockIdx.x * 8 + (threadIdx.x >> 5);
    if (dst >= Nn) return;
    const int lane = threadIdx.x & 31;
    const int half = lane >> 4;
    const int f    = lane & 15;
    const int beg = __ldg(rowptr + dst);
    const int end = __ldg(rowptr + dst + 1);

    float a0 = 0.f, a1 = 0.f, a2 = 0.f, a3 = 0.f, a4 = 0.f;

    for (int e = beg + half; e < end; e += 2) {
        float4 r0 = __ldg(er0 + e);
        float2 r1 = __ldg(er1 + e);
        int src = __float_as_int(r0.x);
        float v = __ldg(x + (size_t)src * 16 + f);
        a0 += r0.y * v; a1 += r0.z * v; a2 += r0.w * v;
        a3 += r1.x * v; a4 += r1.y * v;
    }
    a0 += __shfl_xor_sync(0xffffffffu, a0, 16);
    a1 += __shfl_xor_sync(0xffffffffu, a1, 16);
    a2 += __shfl_xor_sync(0xffffffffu, a2, 16);
    a3 += __shfl_xor_sync(0xffffffffu, a3, 16);
    a4 += __shfl_xor_sync(0xffffffffu, a4, 16);

    if (half == 0) {
        const size_t KS = (size_t)Nn * 16;
        float* zp = z + (size_t)dst * 16 + f;
        zp[0]    = a0;
        zp[KS]   = a1;
        zp[2*KS] = a2;
        zp[3*KS] = a3;
        zp[4*KS] = a4;
    }
}

// ============================================================
// GEMM-sum: h[n] = relu( sum_k z_k[n] @ W[k] + b )
// 128 nodes x 64 outs / CTA, 256 threads, 8x4 register tile.
// Dynamic smem: zsT[KD][132] + ws[KD*64]. 4 CTAs/SM.
// ============================================================
template<int KD>
__global__ void __launch_bounds__(256, 4)
gemmsum_kernel(const float* __restrict__ z,
               const float* __restrict__ W,
               const float* __restrict__ b,
               float* __restrict__ h)
{
    extern __shared__ float smem[];
    float* zsT = smem;               // [KD][132], node-major rows
    float* ws  = smem + KD * 132;    // [KD*64]

    const int t  = threadIdx.x;
    const int n0 = blockIdx.x * 128;
    const int tx = t & 15;           // cols 4tx..4tx+3
    const int ty = t >> 4;           // nodes ty*8..ty*8+7

    float4 acc[8];
#pragma unroll
    for (int r = 0; r < 8; ++r) acc[r] = make_float4(0.f, 0.f, 0.f, 0.f);

#pragma unroll 1
    for (int k = 0; k < 5; ++k) {
        __syncthreads();
        const float* zk = z + (size_t)k * Nn * KD;
        for (int idx = t; idx < 128 * KD; idx += 256) {
            int node = idx / KD;
            int c    = idx - node * KD;
            int n    = n0 + node;
            zsT[c * 132 + node] = (n < Nn) ? zk[(size_t)n * KD + c] : 0.f;
        }
        for (int idx = t; idx < KD * 64; idx += 256)
            ws[idx] = __ldg(W + k * KD * 64 + idx);
        __syncthreads();

#pragma unroll 8
        for (int kk = 0; kk < KD; ++kk) {
            float4 xa = *(const float4*)&zsT[kk * 132 + ty * 8];
            float4 xb = *(const float4*)&zsT[kk * 132 + ty * 8 + 4];
            float4 wv = *(const float4*)&ws[kk * 64 + tx * 4];
            acc[0].x += xa.x * wv.x; acc[0].y += xa.x * wv.y; acc[0].z += xa.x * wv.z; acc[0].w += xa.x * wv.w;
            acc[1].x += xa.y * wv.x; acc[1].y += xa.y * wv.y; acc[1].z += xa.y * wv.z; acc[1].w += xa.y * wv.w;
            acc[2].x += xa.z * wv.x; acc[2].y += xa.z * wv.y; acc[2].z += xa.z * wv.z; acc[2].w += xa.z * wv.w;
            acc[3].x += xa.w * wv.x; acc[3].y += xa.w * wv.y; acc[3].z += xa.w * wv.z; acc[3].w += xa.w * wv.w;
            acc[4].x += xb.x * wv.x; acc[4].y += xb.x * wv.y; acc[4].z += xb.x * wv.z; acc[4].w += xb.x * wv.w;
            acc[5].x += xb.y * wv.x; acc[5].y += xb.y * wv.y; acc[5].z += xb.y * wv.z; acc[5].w += xb.y * wv.w;
            acc[6].x += xb.z * wv.x; acc[6].y += xb.z * wv.y; acc[6].z += xb.z * wv.z; acc[6].w += xb.z * wv.w;
            acc[7].x += xb.w * wv.x; acc[7].y += xb.w * wv.y; acc[7].z += xb.w * wv.z; acc[7].w += xb.w * wv.w;
        }
    }

    float4 bb = *(const float4*)&b[tx * 4];
#pragma unroll
    for (int r = 0; r < 8; ++r) {
        int nl = n0 + ty * 8 + r;
        if (nl >= Nn) break;
        float4 o;
        o.x = fmaxf(acc[r].x + bb.x, 0.f);
        o.y = fmaxf(acc[r].y + bb.y, 0.f);
        o.z = fmaxf(acc[r].z + bb.z, 0.f);
        o.w = fmaxf(acc[r].w + bb.w, 0.f);
        *(float4*)&h[(size_t)nl * 64 + tx * 4] = o;
    }
}

// ============================================================
// Pooling: h already relu'd; sum & max per analytic graph ranges.
// ============================================================
__global__ void pool_kernel(const float* __restrict__ h, float* __restrict__ pooled)
{
    __shared__ float ss[4][64];
    __shared__ float sm[4][64];
    int g     = blockIdx.x;
    int f     = threadIdx.x & 63;
    int strip = threadIdx.x >> 6;
    int start = (g * Nn + Gg - 1) / Gg;
    int end   = ((g + 1) * Nn + Gg - 1) / Gg;

    float s = 0.f, m = 0.f;  // h >= 0
    for (int n = start + strip; n < end; n += 4) {
        float v = __ldg(h + (size_t)n * 64 + f);
        s += v;
        m = fmaxf(m, v);
    }
    ss[strip][f] = s;
    sm[strip][f] = m;
    __syncthreads();
    if (strip == 0) {
        s = ss[0][f] + ss[1][f] + ss[2][f] + ss[3][f];
        m = fmaxf(fmaxf(sm[0][f], sm[1][f]), fmaxf(sm[2][f], sm[3][f]));
        pooled[g * 128 + f]      = s;
        pooled[g * 128 + 64 + f] = m;
    }
}

// ============================================================
// Head: BN -> FC -> log_softmax
// ============================================================
__global__ void head_kernel(const float* __restrict__ pooled,
                            const float* __restrict__ gam,
                            const float* __restrict__ bet,
                            const float* __restrict__ mean,
                            const float* __restrict__ var,
                            const float* __restrict__ fw,
                            const float* __restrict__ fb,
                            float* __restrict__ out)
{
    int g    = blockIdx.x;
    int lane = threadIdx.x;

    float pn[4];
#pragma unroll
    for (int i = 0; i < 4; ++i) {
        int c = lane + 32 * i;
        float p = __ldg(pooled + g * 128 + c);
        float inv = 1.f / sqrtf(__ldg(var + c) + 1e-5f);
        pn[i] = (p - __ldg(mean + c)) * inv * __ldg(gam + c) + __ldg(bet + c);
    }

    float logits[6];
#pragma unroll
    for (int j = 0; j < 6; ++j) {
        float s = 0.f;
#pragma unroll
        for (int i = 0; i < 4; ++i)
            s += pn[i] * __ldg(fw + (lane + 32 * i) * 6 + j);
#pragma unroll
        for (int o = 16; o; o >>= 1)
            s += __shfl_xor_sync(0xffffffffu, s, o);
        logits[j] = s + __ldg(fb + j);
    }

    if (lane == 0) {
        float m = logits[0];
#pragma unroll
        for (int j = 1; j < 6; ++j) m = fmaxf(m, logits[j]);
        float se = 0.f;
#pragma unroll
        for (int j = 0; j < 6; ++j) se += expf(logits[j] - m);
        float lse = m + logf(se);
#pragma unroll
        for (int j = 0; j < 6; ++j) out[g * 6 + j] = logits[j] - lse;
    }
}

// ============================================================
extern "C" void kernel_launch(void* const* d_in, const int* in_sizes, int n_in,
                              void* d_out, int out_size)
{
    const float* x   = (const float*)d_in[0];
    const int*   ei  = (const int*)  d_in[1];
    const float* ea  = (const float*)d_in[2];
    const float* W1  = (const float*)d_in[4];
    const float* b1  = (const float*)d_in[5];
    const float* W2  = (const float*)d_in[6];
    const float* b2  = (const float*)d_in[7];
    const float* W3  = (const float*)d_in[8];
    const float* b3  = (const float*)d_in[9];
    const float* W4  = (const float*)d_in[10];
    const float* b4  = (const float*)d_in[11];
    const float* bng = (const float*)d_in[12];
    const float* bnb = (const float*)d_in[13];
    const float* bnm = (const float*)d_in[14];
    const float* bnv = (const float*)d_in[15];
    const float* fw  = (const float*)d_in[16];
    const float* fb  = (const float*)d_in[17];
    float* out = (float*)d_out;

    float *zb, *h0, *h1, *pl;
    int *cnt, *cur, *rp;
    float4* er0;
    float2* er1;
    cudaGetSymbolAddress((void**)&zb, g_z);
    cudaGetSymbolAddress((void**)&h0, g_h0);
    cudaGetSymbolAddress((void**)&h1, g_h1);
    cudaGetSymbolAddress((void**)&pl, g_pool);
    cudaGetSymbolAddress((void**)&cnt, g_cnt);
    cudaGetSymbolAddress((void**)&cur, g_cursor);
    cudaGetSymbolAddress((void**)&rp, g_rowptr);
    cudaGetSymbolAddress((void**)&er0, g_er0);
    cudaGetSymbolAddress((void**)&er1, g_er1);

    const int EB  = (Ee + 255) / 256;       // 6250
    const int EB2 = (Ee + 511) / 512;       // 3125 (2 edges/thread)
    const int GB  = (Nn + 127) / 128;       // 391
    const int AB  = (Nn + 7) / 8;           // 6250 (one warp per dst)

    const int SM16 = (16 * 132 + 16 * 64) * 4;   // 12544 B
    const int SM64 = (64 * 132 + 64 * 64) * 4;   // 50176 B
    static int smem_set = 0;
    if (!smem_set) {
        cudaFuncSetAttribute(gemmsum_kernel<16>, cudaFuncAttributeMaxDynamicSharedMemorySize, SM16);
        cudaFuncSetAttribute(gemmsum_kernel<64>, cudaFuncAttributeMaxDynamicSharedMemorySize, SM64);
        smem_set = 1;
    }

    // ---- counting sort of edges by dst -> CSR ----
    zero_cnt_kernel<<<(Nn + 255) / 256, 256>>>(cnt);
    hist_kernel<<<EB, 256>>>(ei, cnt);
    scan_kernel<<<1, 1024>>>(cnt, cur, rp);
    permute_kernel<<<EB2, 256>>>(ei, ea, cur, er0, er1);

    // ---- layer 1 (in: x [N,16], raw) ----
    aggregate16_kernel<<<AB, 256>>>(rp, er0, er1, x, zb);
    gemmsum_kernel<16><<<GB, 256, SM16>>>(zb, W1, b1, h0);
    // ---- layer 2 ----
    aggregate64_kernel<<<AB, 256>>>(rp, er0, er1, h0, zb);
    gemmsum_kernel<64><<<GB, 256, SM64>>>(zb, W2, b2, h1);
    // ---- layer 3 ----
    aggregate64_kernel<<<AB, 256>>>(rp, er0, er1, h1, zb);
    gemmsum_kernel<64><<<GB, 256, SM64>>>(zb, W3, b3, h0);
    // ---- layer 4 ----
    aggregate64_kernel<<<AB, 256>>>(rp, er0, er1, h0, zb);
    gemmsum_kernel<64><<<GB, 256, SM64>>>(zb, W4, b4, h1);

    pool_kernel<<<Gg, 256>>>(h1, pl);
    head_kernel<<<Gg, 32>>>(pl, bng, bnb, bnm, bnv, fw, fb, out);
}

// round 11
// speedup vs baseline: 1.1433x; 1.0307x over previous
#include <cuda_runtime.h>
#include <cstdint>
#include <cstddef>

#define Nn 50000
#define Ee 1600000
#define Gg 128
#define Hh 64

typedef unsigned long long ull;

// ---- scratch (device globals) ----
__device__ float g_z[(size_t)5 * Nn * Hh];     // 64 MB: z_k = segment_sum(ea_k * act(h[src]))
__device__ float g_h0[(size_t)Nn * Hh];        // ping
__device__ float g_h1[(size_t)Nn * Hh];        // pong
__device__ float g_pool[Gg * 2 * Hh];

// dst-CSR sort scratch (24 B/edge, split)
__device__ int    g_cnt[Nn];
__device__ int    g_cursor[Nn];
__device__ int    g_rowptr[Nn + 1];
__device__ float4 g_er0[Ee];                   // {src, w0, w1, w2}
__device__ float2 g_er1[Ee];                   // {w3, w4}

// ============================================================
// counting sort by dst: hist -> scan -> permute
// ============================================================
__global__ void zero_cnt_kernel(int* __restrict__ cnt)
{
    unsigned i = blockIdx.x * 256u + threadIdx.x;
    if (i < (unsigned)Nn) cnt[i] = 0;
}

__global__ void hist_kernel(const int* __restrict__ ei, int* __restrict__ cnt)
{
    unsigned e = blockIdx.x * 256u + threadIdx.x;
    if (e < (unsigned)Ee) atomicAdd(&cnt[__ldg(ei + Ee + e)], 1);  // dst
}

__global__ void scan_kernel(const int* __restrict__ cnt,
                            int* __restrict__ cursor,
                            int* __restrict__ rowptr)
{
    __shared__ int tsum[1024];
    const int t  = threadIdx.x;
    const int CH = (Nn + 1023) / 1024;  // 49
    const int base = t * CH;

    int s = 0;
#pragma unroll 1
    for (int i = 0; i < CH; ++i) {
        int idx = base + i;
        if (idx < Nn) s += cnt[idx];
    }
    tsum[t] = s;
    __syncthreads();
    for (int o = 1; o < 1024; o <<= 1) {
        int u = (t >= o) ? tsum[t - o] : 0;
        __syncthreads();
        tsum[t] += u;
        __syncthreads();
    }
    int run = tsum[t] - s;  // exclusive
#pragma unroll 1
    for (int i = 0; i < CH; ++i) {
        int idx = base + i;
        if (idx < Nn) {
            cursor[idx] = run;
            rowptr[idx] = run;
            run += cnt[idx];
        }
    }
    if (t == 0) rowptr[Nn] = Ee;
}

__global__ void permute_kernel(const int* __restrict__ ei,
                               const float* __restrict__ ea,
                               int* __restrict__ cursor,
                               float4* __restrict__ er0,
                               float2* __restrict__ er1)
{
    unsigned e = blockIdx.x * 256u + threadIdx.x;
    if (e >= (unsigned)Ee) return;
    int src = __ldg(ei + e);
    int dst = __ldg(ei + Ee + e);
    const float* p = ea + (size_t)e * 5;
    float w0 = __ldg(p), w1 = __ldg(p + 1), w2 = __ldg(p + 2),
          w3 = __ldg(p + 3), w4 = __ldg(p + 4);
    int pos = atomicAdd(&cursor[dst], 1);
    er0[pos] = make_float4(__int_as_float(src), w0, w1, w2);
    er1[pos] = make_float2(w3, w4);
}

// ============================================================
// Aggregate (H=64): one warp per dst node; 2 edges in flight.
// Lanes 0-15 process even edges, 16-31 odd edges; each lane = 4 feats
// (float4 gather). Halves combined via shfl_xor(16) at the end.
// ============================================================
__global__ void aggregate64_kernel(const int* __restrict__ rowptr,
                                   const float4* __restrict__ er0,
                                   const float2* __restrict__ er1,
                                   const float* __restrict__ x,
                                   float* __restrict__ z)
{
    int dst = blockIdx.x * 8 + (threadIdx.x >> 5);
    if (dst >= Nn) return;
    const int lane = threadIdx.x & 31;
    const int hl   = lane & 15;   // feat group: feats 4*hl..4*hl+3
    const int par  = lane >> 4;   // edge parity
    const int beg = __ldg(rowptr + dst);
    const int end = __ldg(rowptr + dst + 1);

    float4 a0 = {0.f,0.f,0.f,0.f}, a1 = a0, a2 = a0, a3 = a0, a4 = a0;

#pragma unroll 2
    for (int e = beg + par; e < end; e += 2) {
        float4 r0 = __ldg(er0 + e);
        float2 r1 = __ldg(er1 + e);
        int src = __float_as_int(r0.x);
        float4 v = __ldg((const float4*)(x + (size_t)src * 64 + hl * 4));
        a0.x += r0.y*v.x; a0.y += r0.y*v.y; a0.z += r0.y*v.z; a0.w += r0.y*v.w;
        a1.x += r0.z*v.x; a1.y += r0.z*v.y; a1.z += r0.z*v.z; a1.w += r0.z*v.w;
        a2.x += r0.w*v.x; a2.y += r0.w*v.y; a2.z += r0.w*v.z; a2.w += r0.w*v.w;
        a3.x += r1.x*v.x; a3.y += r1.x*v.y; a3.z += r1.x*v.z; a3.w += r1.x*v.w;
        a4.x += r1.y*v.x; a4.y += r1.y*v.y; a4.z += r1.y*v.z; a4.w += r1.y*v.w;
    }

    // combine parity halves (same feats live at lane and lane^16)
#define CMB(f) f += __shfl_xor_sync(0xffffffffu, f, 16)
    CMB(a0.x); CMB(a0.y); CMB(a0.z); CMB(a0.w);
    CMB(a1.x); CMB(a1.y); CMB(a1.z); CMB(a1.w);
    CMB(a2.x); CMB(a2.y); CMB(a2.z); CMB(a2.w);
    CMB(a3.x); CMB(a3.y); CMB(a3.z); CMB(a3.w);
    CMB(a4.x); CMB(a4.y); CMB(a4.z); CMB(a4.w);
#undef CMB

    if (par == 0) {
        const size_t KS = (size_t)Nn * 64;
        float* zp = z + (size_t)dst * 64 + hl * 4;
        *(float4*)(zp)        = a0;
        *(float4*)(zp + KS)   = a1;
        *(float4*)(zp + 2*KS) = a2;
        *(float4*)(zp + 3*KS) = a3;
        *(float4*)(zp + 4*KS) = a4;
    }
}

// ============================================================
// Aggregate (F=16, layer 1, raw x): warp splits in 2 halves over edges.
// ============================================================
__global__ void aggregate16_kernel(const int* __restrict__ rowptr,
                                   const float4* __restrict__ er0,
                                   const float2* __restrict__ er1,
                                   const float* __restrict__ x,
                                   float* __restrict__ z)
{
    int dst = blockIdx.x * 8 + (threadIdx.x >> 5);
    if (dst >= Nn) return;
    const int lane = threadIdx.x & 31;
    const int half = lane >> 4;
    const int f    = lane & 15;
    const int beg = __ldg(rowptr + dst);
    const int end = __ldg(rowptr + dst + 1);

    float a0 = 0.f, a1 = 0.f, a2 = 0.f, a3 = 0.f, a4 = 0.f;

    for (int e = beg + half; e < end; e += 2) {
        float4 r0 = __ldg(er0 + e);
        float2 r1 = __ldg(er1 + e);
        int src = __float_as_int(r0.x);
        float v = __ldg(x + (size_t)src * 16 + f);
        a0 += r0.y * v; a1 += r0.z * v; a2 += r0.w * v;
        a3 += r1.x * v; a4 += r1.y * v;
    }
    a0 += __shfl_xor_sync(0xffffffffu, a0, 16);
    a1 += __shfl_xor_sync(0xffffffffu, a1, 16);
    a2 += __shfl_xor_sync(0xffffffffu, a2, 16);
    a3 += __shfl_xor_sync(0xffffffffu, a3, 16);
    a4 += __shfl_xor_sync(0xffffffffu, a4, 16);

    if (half == 0) {
        const size_t KS = (size_t)Nn * 16;
        float* zp = z + (size_t)dst * 16 + f;
        zp[0]    = a0;
        zp[KS]   = a1;
        zp[2*KS] = a2;
        zp[3*KS] = a3;
        zp[4*KS] = a4;
    }
}

// ============================================================
// GEMM-sum: h[n] = relu( sum_k z_k[n] @ W[k] + b )
// 128 nodes x 64 outs / CTA, 256 threads, 8x4 register tile.
// Inner loop uses fma.rn.f32x2 (2 fp32 FMAs per fma-pipe issue);
// (v,v) operand packed in-loop via mov.b64 (ALU pipe).
// Dynamic smem: zsT[KD][132] + ws[KD*64]. 4 CTAs/SM.
// ============================================================
template<int KD>
__global__ void __launch_bounds__(256, 4)
gemmsum_kernel(const float* __restrict__ z,
               const float* __restrict__ W,
               const float* __restrict__ b,
               float* __restrict__ h)
{
    extern __shared__ float smem[];
    float* zsT = smem;               // [KD][132], node-major rows
    float* ws  = smem + KD * 132;    // [KD*64]

    const int t  = threadIdx.x;
    const int n0 = blockIdx.x * 128;
    const int tx = t & 15;           // cols 4tx..4tx+3
    const int ty = t >> 4;           // nodes ty*8..ty*8+7

    ull acc[8][2];
#pragma unroll
    for (int r = 0; r < 8; ++r) { acc[r][0] = 0ull; acc[r][1] = 0ull; }

#pragma unroll 1
    for (int k = 0; k < 5; ++k) {
        __syncthreads();
        const float* zk = z + (size_t)k * Nn * KD;
        for (int idx = t; idx < 128 * KD; idx += 256) {
            int node = idx / KD;
            int c    = idx - node * KD;
            int n    = n0 + node;
            zsT[c * 132 + node] = (n < Nn) ? zk[(size_t)n * KD + c] : 0.f;
        }
        for (int idx = t; idx < KD * 64; idx += 256)
            ws[idx] = __ldg(W + k * KD * 64 + idx);
        __syncthreads();

#pragma unroll 8
        for (int kk = 0; kk < KD; ++kk) {
            float4 xa = *(const float4*)&zsT[kk * 132 + ty * 8];
            float4 xb = *(const float4*)&zsT[kk * 132 + ty * 8 + 4];
            float4 wv = *(const float4*)&ws[kk * 64 + tx * 4];
            ull w01, w23;
            asm("mov.b64 %0,{%1,%2};" : "=l"(w01) : "f"(wv.x), "f"(wv.y));
            asm("mov.b64 %0,{%1,%2};" : "=l"(w23) : "f"(wv.z), "f"(wv.w));
#define STEP(r, v) { ull vv; \
            asm("mov.b64 %0,{%1,%1};" : "=l"(vv) : "f"(v)); \
            asm("fma.rn.f32x2 %0,%1,%2,%0;" : "+l"(acc[r][0]) : "l"(vv), "l"(w01)); \
            asm("fma.rn.f32x2 %0,%1,%2,%0;" : "+l"(acc[r][1]) : "l"(vv), "l"(w23)); }
            STEP(0, xa.x) STEP(1, xa.y) STEP(2, xa.z) STEP(3, xa.w)
            STEP(4, xb.x) STEP(5, xb.y) STEP(6, xb.z) STEP(7, xb.w)
#undef STEP
        }
    }

    float4 bb = *(const float4*)&b[tx * 4];
#pragma unroll
    for (int r = 0; r < 8; ++r) {
        int nl = n0 + ty * 8 + r;
        if (nl >= Nn) break;
        float lo0, lo1, hi0, hi1;
        asm("mov.b64 {%0,%1},%2;" : "=f"(lo0), "=f"(lo1) : "l"(acc[r][0]));
        asm("mov.b64 {%0,%1},%2;" : "=f"(hi0), "=f"(hi1) : "l"(acc[r][1]));
        float4 o;
        o.x = fmaxf(lo0 + bb.x, 0.f);
        o.y = fmaxf(lo1 + bb.y, 0.f);
        o.z = fmaxf(hi0 + bb.z, 0.f);
        o.w = fmaxf(hi1 + bb.w, 0.f);
        *(float4*)&h[(size_t)nl * 64 + tx * 4] = o;
    }
}

// ============================================================
// Pooling: h already relu'd; sum & max per analytic graph ranges.
// ============================================================
__global__ void pool_kernel(const float* __restrict__ h, float* __restrict__ pooled)
{
    __shared__ float ss[4][64];
    __shared__ float sm[4][64];
    int g     = blockIdx.x;
    int f     = threadIdx.x & 63;
    int strip = threadIdx.x >> 6;
    int start = (g * Nn + Gg - 1) / Gg;
    int end   = ((g + 1) * Nn + Gg - 1) / Gg;

    float s = 0.f, m = 0.f;  // h >= 0
    for (int n = start + strip; n < end; n += 4) {
        float v = __ldg(h + (size_t)n * 64 + f);
        s += v;
        m = fmaxf(m, v);
    }
    ss[strip][f] = s;
    sm[strip][f] = m;
    __syncthreads();
    if (strip == 0) {
        s = ss[0][f] + ss[1][f] + ss[2][f] + ss[3][f];
        m = fmaxf(fmaxf(sm[0][f], sm[1][f]), fmaxf(sm[2][f], sm[3][f]));
        pooled[g * 128 + f]      = s;
        pooled[g * 128 + 64 + f] = m;
    }
}

// ============================================================
// Head: BN -> FC -> log_softmax
// ============================================================
__global__ void head_kernel(const float* __restrict__ pooled,
                            const float* __restrict__ gam,
                            const float* __restrict__ bet,
                            const float* __restrict__ mean,
                            const float* __restrict__ var,
                            const float* __restrict__ fw,
                            const float* __restrict__ fb,
                            float* __restrict__ out)
{
    int g    = blockIdx.x;
    int lane = threadIdx.x;

    float pn[4];
#pragma unroll
    for (int i = 0; i < 4; ++i) {
        int c = lane + 32 * i;
        float p = __ldg(pooled + g * 128 + c);
        float inv = 1.f / sqrtf(__ldg(var + c) + 1e-5f);
        pn[i] = (p - __ldg(mean + c)) * inv * __ldg(gam + c) + __ldg(bet + c);
    }

    float logits[6];
#pragma unroll
    for (int j = 0; j < 6; ++j) {
        float s = 0.f;
#pragma unroll
        for (int i = 0; i < 4; ++i)
            s += pn[i] * __ldg(fw + (lane + 32 * i) * 6 + j);
#pragma unroll
        for (int o = 16; o; o >>= 1)
            s += __shfl_xor_sync(0xffffffffu, s, o);
        logits[j] = s + __ldg(fb + j);
    }

    if (lane == 0) {
        float m = logits[0];
#pragma unroll
        for (int j = 1; j < 6; ++j) m = fmaxf(m, logits[j]);
        float se = 0.f;
#pragma unroll
        for (int j = 0; j < 6; ++j) se += expf(logits[j] - m);
        float lse = m + logf(se);
#pragma unroll
        for (int j = 0; j < 6; ++j) out[g * 6 + j] = logits[j] - lse;
    }
}

// ============================================================
extern "C" void kernel_launch(void* const* d_in, const int* in_sizes, int n_in,
                              void* d_out, int out_size)
{
    const float* x   = (const float*)d_in[0];
    const int*   ei  = (const int*)  d_in[1];
    const float* ea  = (const float*)d_in[2];
    const float* W1  = (const float*)d_in[4];
    const float* b1  = (const float*)d_in[5];
    const float* W2  = (const float*)d_in[6];
    const float* b2  = (const float*)d_in[7];
    const float* W3  = (const float*)d_in[8];
    const float* b3  = (const float*)d_in[9];
    const float* W4  = (const float*)d_in[10];
    const float* b4  = (const float*)d_in[11];
    const float* bng = (const float*)d_in[12];
    const float* bnb = (const float*)d_in[13];
    const float* bnm = (const float*)d_in[14];
    const float* bnv = (const float*)d_in[15];
    const float* fw  = (const float*)d_in[16];
    const float* fb  = (const float*)d_in[17];
    float* out = (float*)d_out;

    float *zb, *h0, *h1, *pl;
    int *cnt, *cur, *rp;
    float4* er0;
    float2* er1;
    cudaGetSymbolAddress((void**)&zb, g_z);
    cudaGetSymbolAddress((void**)&h0, g_h0);
    cudaGetSymbolAddress((void**)&h1, g_h1);
    cudaGetSymbolAddress((void**)&pl, g_pool);
    cudaGetSymbolAddress((void**)&cnt, g_cnt);
    cudaGetSymbolAddress((void**)&cur, g_cursor);
    cudaGetSymbolAddress((void**)&rp, g_rowptr);
    cudaGetSymbolAddress((void**)&er0, g_er0);
    cudaGetSymbolAddress((void**)&er1, g_er1);

    const int EB = (Ee + 255) / 256;        // 6250
    const int GB = (Nn + 127) / 128;        // 391
    const int AB = (Nn + 7) / 8;            // 6250 (one warp per dst)

    const int SM16 = (16 * 132 + 16 * 64) * 4;   // 12544 B
    const int SM64 = (64 * 132 + 64 * 64) * 4;   // 50176 B
    static int smem_set = 0;
    if (!smem_set) {
        cudaFuncSetAttribute(gemmsum_kernel<16>, cudaFuncAttributeMaxDynamicSharedMemorySize, SM16);
        cudaFuncSetAttribute(gemmsum_kernel<64>, cudaFuncAttributeMaxDynamicSharedMemorySize, SM64);
        smem_set = 1;
    }

    // ---- counting sort of edges by dst -> CSR ----
    zero_cnt_kernel<<<(Nn + 255) / 256, 256>>>(cnt);
    hist_kernel<<<EB, 256>>>(ei, cnt);
    scan_kernel<<<1, 1024>>>(cnt, cur, rp);
    permute_kernel<<<EB, 256>>>(ei, ea, cur, er0, er1);

    // ---- layer 1 (in: x [N,16], raw) ----
    aggregate16_kernel<<<AB, 256>>>(rp, er0, er1, x, zb);
    gemmsum_kernel<16><<<GB, 256, SM16>>>(zb, W1, b1, h0);
    // ---- layer 2 ----
    aggregate64_kernel<<<AB, 256>>>(rp, er0, er1, h0, zb);
    gemmsum_kernel<64><<<GB, 256, SM64>>>(zb, W2, b2, h1);
    // ---- layer 3 ----
    aggregate64_kernel<<<AB, 256>>>(rp, er0, er1, h1, zb);
    gemmsum_kernel<64><<<GB, 256, SM64>>>(zb, W3, b3, h0);
    // ---- layer 4 ----
    aggregate64_kernel<<<AB, 256>>>(rp, er0, er1, h0, zb);
    gemmsum_kernel<64><<<GB, 256, SM64>>>(zb, W4, b4, h1);

    pool_kernel<<<Gg, 256>>>(h1, pl);
    head_kernel<<<Gg, 32>>>(pl, bng, bnb, bnm, bnv, fw, fb, out);
}